// round 17
// baseline (speedup 1.0000x reference)
#include <cuda_runtime.h>
#include <cstdint>

#define Bn 64
#define Tn 2048
#define Dn 512
#define Un 32
#define FULLM 0xffffffffu
typedef unsigned long long ull;

// ---------------- packed f32x2 ops ----------------
__device__ __forceinline__ ull fma2(ull a, ull b, ull c) {
    ull d;
    asm("fma.rn.f32x2 %0, %1, %2, %3;" : "=l"(d) : "l"(a), "l"(b), "l"(c));
    return d;
}
__device__ __forceinline__ ull add2(ull a, ull b) {
    ull d;
    asm("add.rn.f32x2 %0, %1, %2;" : "=l"(d) : "l"(a), "l"(b));
    return d;
}
__device__ __forceinline__ void unpack2(ull a, float& lo, float& hi) {
    asm("mov.b64 {%0, %1}, %2;" : "=f"(lo), "=f"(hi) : "l"(a));
}
__device__ __forceinline__ ull pack2(float lo, float hi) {
    ull d;
    asm("mov.b64 %0, {%1, %2};" : "=l"(d) : "f"(lo), "f"(hi));
    return d;
}
__device__ __forceinline__ void cp16(float* smem_ptr, const float* gptr) {
    unsigned saddr = (unsigned)__cvta_generic_to_shared(smem_ptr);
    asm volatile("cp.async.cg.shared.global [%0], [%1], 16;" :: "r"(saddr), "l"(gptr));
}
__device__ __forceinline__ void pbar(int id) {
    asm volatile("bar.sync %0, %1;" :: "r"(id), "r"(64) : "memory");
}

#define NCHUNK 32
#define NJOBS (NCHUNK * Bn)   // 2048 gemm chunk-jobs
#define NBLOCKS 304           // 152 SMs x occ2 (256-thread blocks)
#define NVIT 16               // viterbi SMs (4 batches each)

#define VWSTRIDE 1536         // per-batch viterbi smem: abuf 256 | pmap 1024 | anch 128
#define SMEM_BYTES 65536      // gemm sx 64KB; viterbi uses 6KB of it

// scratch: 16 MB logits + 4 MB backpointers + control block
__device__ float g_logits[(size_t)Bn * Tn * Un];
__device__ unsigned char g_bp[(size_t)Bn * Tn * 32];
// [0,2048) chunk flags (b*32+c); [2048,2304) sm role; [2304] vit ctr; [2305] job ctr
__device__ int g_ctrl[2048 + 256 + 2];

// ================= GEMM job: 64 rows, 256 threads (8 warps x 8 rows) ==========
__device__ void gemm_role(int c, int b, const float* __restrict__ x,
                          const float* __restrict__ W,
                          const float* __restrict__ bias, char* smem) {
    float* sx = (float*)smem;  // 2 x 64 x 128 floats (64KB)
    const int tid = threadIdx.x;
    const size_t row0 = (size_t)b * Tn + c * 64;

    {
        const float* gsrc = x + row0 * Dn;
#pragma unroll
        for (int q = 0; q < 8; q++) {
            int lin = tid + 256 * q;
            int rr = lin >> 5, cc = lin & 31;
            cp16(sx + rr * 128 + cc * 4, gsrc + (size_t)rr * Dn + cc * 4);
        }
        asm volatile("cp.async.commit_group;");
    }

    const int w = tid >> 5, u = tid & 31;
    const int wr0 = w * 8;

    ull acc[8];
#pragma unroll
    for (int r = 0; r < 8; r++) acc[r] = 0ull;

    for (int kt = 0; kt < 4; kt++) {
        if (kt < 3) {
            const float* gsrc = x + row0 * Dn + (kt + 1) * 128;
            float* sdst = sx + ((kt + 1) & 1) * 8192;
#pragma unroll
            for (int q = 0; q < 8; q++) {
                int lin = tid + 256 * q;
                int rr = lin >> 5, cc = lin & 31;
                cp16(sdst + rr * 128 + cc * 4, gsrc + (size_t)rr * Dn + cc * 4);
            }
            asm volatile("cp.async.commit_group;");
            asm volatile("cp.async.wait_group 1;");
        } else {
            asm volatile("cp.async.wait_group 0;");
        }
        __syncthreads();

        const float* xbuf = sx + (kt & 1) * 8192;
        const float* wg = W + (kt * 128) * Un + u;
        for (int k8 = 0; k8 < 128; k8 += 8) {
            float wv0 = __ldg(wg + (k8 + 0) * Un);
            float wv1 = __ldg(wg + (k8 + 1) * Un);
            float wv2 = __ldg(wg + (k8 + 2) * Un);
            float wv3 = __ldg(wg + (k8 + 3) * Un);
            float wv4 = __ldg(wg + (k8 + 4) * Un);
            float wv5 = __ldg(wg + (k8 + 5) * Un);
            float wv6 = __ldg(wg + (k8 + 6) * Un);
            float wv7 = __ldg(wg + (k8 + 7) * Un);
            ull wp0 = pack2(wv0, wv1), wp1 = pack2(wv2, wv3);
            ull wp2 = pack2(wv4, wv5), wp3 = pack2(wv6, wv7);
#pragma unroll
            for (int r = 0; r < 8; r++) {
                const float* xr = xbuf + (wr0 + r) * 128 + k8;
                ulonglong2 x0 = *(const ulonglong2*)(xr);
                ulonglong2 x1 = *(const ulonglong2*)(xr + 4);
                acc[r] = fma2(x0.x, wp0, acc[r]);
                acc[r] = fma2(x0.y, wp1, acc[r]);
                acc[r] = fma2(x1.x, wp2, acc[r]);
                acc[r] = fma2(x1.y, wp3, acc[r]);
            }
        }
        __syncthreads();
    }

    float bu = bias[u];
#pragma unroll
    for (int r = 0; r < 8; r++) {
        float lo, hi;
        unpack2(acc[r], lo, hi);
        g_logits[(row0 + wr0 + r) * Un + u] = lo + hi + bu;
    }
    __syncthreads();
    if (tid == 0) {
        __threadfence();
        atomicExch(&g_ctrl[b * NCHUNK + c], 1);
    }
}

// ================= Viterbi: alpha warp (value chain only) ======================
__device__ __forceinline__ float ldclamp(const float* lg, int t, int tmax, int j) {
    int ti = t <= tmax ? t : tmax;
    return __ldg(lg + ti * Un + j);
}

__device__ __forceinline__ float vstepA(int t, float lgt, const ull* tcp,
                                        float* abuf, int j, int barid) {
    pbar(barid);  // pair barrier: prior stores visible, resolver synced
    const ulonglong2* ap = (const ulonglong2*)(abuf + ((t - 1) & 1) * 32);
    float m[16];
#pragma unroll
    for (int q = 0; q < 8; q++) {
        ulonglong2 a = ap[q];  // broadcast LDS.128
        ull s0 = add2(a.x, tcp[2 * q]);
        ull s1 = add2(a.y, tcp[2 * q + 1]);
        float v0, v1, v2, v3;
        unpack2(s0, v0, v1);
        unpack2(s1, v2, v3);
        m[2 * q] = fmaxf(v0, v1);
        m[2 * q + 1] = fmaxf(v2, v3);
    }
#pragma unroll
    for (int s = 1; s < 16; s <<= 1) {
#pragma unroll
        for (int i = 0; i < 16; i += (s << 1)) m[i] = fmaxf(m[i], m[i + s]);
    }
    float na = m[0] + lgt;
    abuf[(t & 1) * 32 + j] = na;
    return na;
}

// ================= Viterbi: resolver warp (argmax + bp, off-chain) =============
__device__ __forceinline__ void vstepR(int t, const ull* tcp, const float* abuf,
                                       unsigned char* gbp, int j, int barid) {
    pbar(barid);
    const ulonglong2* ap = (const ulonglong2*)(abuf + ((t - 1) & 1) * 32);
    float qv[8];
    int qi[8];
#pragma unroll
    for (int q = 0; q < 8; q++) {
        ulonglong2 a = ap[q];
        ull s0 = add2(a.x, tcp[2 * q]);
        ull s1 = add2(a.y, tcp[2 * q + 1]);
        float v0, v1, v2, v3;
        unpack2(s0, v0, v1);
        unpack2(s1, v2, v3);
        // strict '>' so lower index wins ties (matches jnp.argmax)
        bool g0 = v1 > v0; float m0 = fmaxf(v0, v1); int i0 = g0 ? 4 * q + 1 : 4 * q;
        bool g1 = v3 > v2; float m1 = fmaxf(v2, v3); int i1 = g1 ? 4 * q + 3 : 4 * q + 2;
        bool gc = m1 > m0;
        qv[q] = fmaxf(m0, m1);
        qi[q] = gc ? i1 : i0;
    }
#pragma unroll
    for (int s = 1; s < 8; s <<= 1) {
#pragma unroll
        for (int i = 0; i < 8; i += (s << 1)) {
            bool g = qv[i + s] > qv[i];
            qv[i] = fmaxf(qv[i], qv[i + s]);
            qi[i] = g ? qi[i + s] : qi[i];
        }
    }
    gbp[t * 32 + j] = (unsigned char)qi[0];
}

__device__ __forceinline__ void waitchunk(int b, int c) {
    if (c > NCHUNK - 1) c = NCHUNK - 1;
    volatile int* f = &g_ctrl[b * NCHUNK + c];
    while (*f == 0) {}
    __threadfence();  // acquire
}

__device__ void alpha_warp(int b, const float* __restrict__ trans,
                           const int* __restrict__ nwords, char* wsm, int barid) {
    float* abuf = (float*)wsm;
    const int j = threadIdx.x & 31;
    int len = nwords[b];
    if (len < 1) len = 1;
    if (len > Tn) len = Tn;
    const int tmax = len - 1;

    const float* lg = g_logits + (size_t)b * Tn * Un;

    ull tcp[16];
#pragma unroll
    for (int p = 0; p < 16; p++)
        tcp[p] = pack2(__ldg(trans + (2 * p) * Un + j),
                       __ldg(trans + (2 * p + 1) * Un + j));

    waitchunk(b, 0);
    abuf[j] = __ldg(lg + j);  // alpha0, parity 0

    float pl0 = ldclamp(lg, 1, tmax, j);
    float pl1 = ldclamp(lg, 2, tmax, j);
    float pl2 = ldclamp(lg, 3, tmax, j);
    float pl3 = ldclamp(lg, 4, tmax, j);

    int t = 1;
    for (; t + 3 <= tmax; t += 4) {
        if ((t & 63) == 1) waitchunk(b, (t >> 6) + 1);  // covers prefetch reach
        float n0 = ldclamp(lg, t + 4, tmax, j);
        float n1 = ldclamp(lg, t + 5, tmax, j);
        float n2 = ldclamp(lg, t + 6, tmax, j);
        float n3 = ldclamp(lg, t + 7, tmax, j);
        vstepA(t, pl0, tcp, abuf, j, barid);
        vstepA(t + 1, pl1, tcp, abuf, j, barid);
        vstepA(t + 2, pl2, tcp, abuf, j, barid);
        vstepA(t + 3, pl3, tcp, abuf, j, barid);
        pl0 = n0; pl1 = n1; pl2 = n2; pl3 = n3;
    }
    for (; t <= tmax; t++) {
        if ((t & 63) == 1) waitchunk(b, (t >> 6) + 1);
        vstepA(t, pl0, tcp, abuf, j, barid);
        pl0 = pl1; pl1 = pl2; pl2 = pl3;
    }
    pbar(barid);  // final: expose abuf[tmax&1] to resolver
}

__device__ void resolver_warp(int b, const float* __restrict__ trans,
                              float* __restrict__ out, int write_pred,
                              int write_score, long long score_off,
                              const int* __restrict__ nwords, char* wsm, int barid) {
    float* abuf = (float*)wsm;
    unsigned char* pmap = (unsigned char*)(wsm + 256);
    int* anch = (int*)(wsm + 256 + 1024);
    const int j = threadIdx.x & 31;
    int len = nwords[b];
    if (len < 1) len = 1;
    if (len > Tn) len = Tn;
    const int tmax = len - 1;

    unsigned char* gbp = g_bp + (size_t)b * Tn * 32;

    ull tcp[16];
#pragma unroll
    for (int p = 0; p < 16; p++)
        tcp[p] = pack2(__ldg(trans + (2 * p) * Un + j),
                       __ldg(trans + (2 * p + 1) * Un + j));

    for (int t = 1; t <= tmax; t++) vstepR(t, tcp, abuf, gbp, j, barid);
    pbar(barid);  // final alpha published
    __threadfence_block();  // order our bp STGs before this warp re-reads them
    __syncwarp();

    // final warp argmax over abuf[tmax&1], lowest-index tie-break
    float bv = abuf[(tmax & 1) * 32 + j];
    int bi = j;
#pragma unroll
    for (int off = 16; off >= 1; off >>= 1) {
        float ov = __shfl_xor_sync(FULLM, bv, off);
        int oi = __shfl_xor_sync(FULLM, bi, off);
        if (ov > bv || (ov == bv && oi < bi)) { bv = ov; bi = oi; }
    }
    const int last_tag = bi;
    if (write_score && j == 0) out[score_off + b] = bv;

    if (write_pred) {
        // per-chunk backward maps: lane j = origin e, r = chunk
        int tg[32];
#pragma unroll
        for (int r = 0; r < 32; r++) tg[r] = j;
        for (int s = 0; s < 64; s++) {
#pragma unroll
            for (int r = 0; r < 32; r++) {
                int th = (r + 1) << 6;
                if (th > tmax) th = tmax;
                int tt = th - s;
                if (tt > (r << 6)) tg[r] = gbp[tt * 32 + tg[r]];
            }
        }
#pragma unroll
        for (int r = 0; r < 32; r++) pmap[r * 32 + j] = (unsigned char)tg[r];
        __syncwarp();

        const int cmax = tmax >> 6;
        if (j == 0) {
            int a = last_tag;
            for (int c = cmax; c >= 0; --c) {
                a = pmap[c * 32 + a];
                anch[c] = a;  // tag @ c*64
            }
        }
        for (int tt = tmax + j; tt < Tn; tt += 32)
            out[(size_t)b * Tn + tt] = (float)last_tag;
        __syncwarp();

        if (j <= cmax) {
            int thi2 = (j == cmax) ? tmax : ((j + 1) << 6);
            int tg2 = (j == cmax) ? last_tag : anch[j + 1];
            for (int tt = thi2; tt > (j << 6); --tt) {
                tg2 = gbp[tt * 32 + tg2];
                out[(size_t)b * Tn + tt - 1] = (float)tg2;
            }
        }
    }
}

// ================= persistent fused kernel with SM-role isolation ==============
__global__ __launch_bounds__(256, 2) void crf_fused(const float* __restrict__ x,
                                                    const int* __restrict__ nwords,
                                                    const float* __restrict__ W,
                                                    const float* __restrict__ trans,
                                                    const float* __restrict__ bias,
                                                    float* __restrict__ out,
                                                    int write_pred, int write_score,
                                                    long long score_off) {
    extern __shared__ char smem[];
    __shared__ int s_role;
    __shared__ int s_vb;
    __shared__ int s_job;

    const int tid = threadIdx.x;
    if (tid == 0) {
        unsigned smid;
        asm("mov.u32 %0, %%smid;" : "=r"(smid));
        int* rp = &g_ctrl[2048 + (smid & 255)];
        int r = atomicCAS(rp, 0, 1);
        if (r == 0) {
            int vb = atomicAdd(&g_ctrl[2304], 1);
            if (vb < NVIT) {
                s_vb = vb;
                atomicExch(rp, 3);
                s_role = 1;
            } else {
                atomicExch(rp, 2);
                s_role = 2;
            }
        } else {
            volatile int* vp = rp;
            int v;
            while ((v = *vp) < 2) {}
            s_role = (v == 3) ? 0 : 2;  // leave viterbi SMs uncontended
        }
    }
    __syncthreads();
    const int role = s_role;
    if (role == 0) return;

    if (role == 1) {
        const int w = tid >> 5;        // 0..7
        const int pairid = w & 3;      // batch slot, SMSP = pair
        const int b = 4 * s_vb + pairid;
        char* wsm = smem + pairid * VWSTRIDE;
        const int barid = 1 + pairid;  // named barrier per pair (ids 1..4)
        if (w < 4)
            alpha_warp(b, trans, nwords, wsm, barid);
        else
            resolver_warp(b, trans, out, write_pred, write_score, score_off,
                          nwords, wsm, barid);
        return;
    }
    // gemm worker: pull chunk jobs (c-major -> chunk 0 of all batches first)
    while (true) {
        if (tid == 0) s_job = atomicAdd(&g_ctrl[2305], 1);
        __syncthreads();
        int job = s_job;
        if (job >= NJOBS) break;
        gemm_role(job >> 6, job & 63, x, W, bias, smem);
        __syncthreads();
    }
}

// ---------------- launch ----------------
extern "C" void kernel_launch(void* const* d_in, const int* in_sizes, int n_in,
                              void* d_out, int out_size) {
    const float* x = (const float*)d_in[0];
    const int* nwords = (const int*)d_in[1];
    const float* W = (const float*)d_in[2];
    const float* trans = (const float*)d_in[3];
    const float* bias = (const float*)d_in[4];
    float* out = (float*)d_out;

    const int BT = Bn * Tn;
    int write_pred = 1, write_score = 0;
    long long score_off = BT;
    if (out_size >= BT + Bn) {
        write_score = 1;
    } else if (out_size == Bn) {
        write_pred = 0;
        write_score = 1;
        score_off = 0;
    }

    static int* ctrl_ptr = nullptr;
    if (!ctrl_ptr) cudaGetSymbolAddress((void**)&ctrl_ptr, g_ctrl);

    cudaFuncSetAttribute(crf_fused, cudaFuncAttributeMaxDynamicSharedMemorySize, SMEM_BYTES);

    cudaMemsetAsync(ctrl_ptr, 0, (2048 + 256 + 2) * sizeof(int));
    crf_fused<<<NBLOCKS, 256, SMEM_BYTES>>>(x, nwords, W, trans, bias, out,
                                            write_pred, write_score, score_off);
}